// round 5
// baseline (speedup 1.0000x reference)
#include <cuda_runtime.h>

#define TT 32
#define PP 16
#define NN 65536
#define HH 128
#define NTHREADS 256
#define NBLOCKS 512          // 512 blocks * 128 points/block = 65536
#define PAIRS 4              // warp pairs per block (8 warps)
#define PTS_PER_BLOCK 128

#define OFF_ARG (TT * NN * 3)      // 6291456
#define OFF_TL  (OFF_ARG + NN)     // 6356992

__device__ __forceinline__ unsigned long long packrep(float a) {
    unsigned long long r;
    asm("mov.b64 %0, {%1, %1};" : "=l"(r) : "f"(a));
    return r;
}
__device__ __forceinline__ void fma2(unsigned long long& d, unsigned long long a, unsigned long long b) {
    asm("fma.rn.f32x2 %0, %1, %2, %0;" : "+l"(d) : "l"(a), "l"(b));
}
__device__ __forceinline__ unsigned long long add2(unsigned long long a, unsigned long long b) {
    unsigned long long r;
    asm("add.rn.f32x2 %0, %1, %2;" : "=l"(r) : "l"(a), "l"(b));
    return r;
}
__device__ __forceinline__ void unpack2(unsigned long long v, float& lo, float& hi) {
    asm("mov.b64 {%0, %1}, %2;" : "=f"(lo), "=f"(hi) : "l"(v));
}

__global__ void __launch_bounds__(NTHREADS) fused_kernel(
    const float* __restrict__ cano, const float* __restrict__ w1,
    const float* __restrict__ b1, const float* __restrict__ w2,
    const float* __restrict__ b2, const float* __restrict__ p6d,
    const float* __restrict__ pt, const float* __restrict__ gum,
    float* __restrict__ out)
{
    __shared__ float4 s_w1[HH];                        // w1 row + b1
    __shared__ __align__(16) float2 s_w2p[HH][8];      // w2 packed over p-pairs
    __shared__ float2 s_b2p[8];
    __shared__ __align__(16) float s_R[TT * PP][12];   // R rows + t
    __shared__ unsigned long long s_part[PAIRS][8][32];// partial seg from odd warp
    __shared__ int s_sel[PAIRS][32];                   // selection per point

    const int tid = threadIdx.x;

    // ---- stage weights into shared memory ----
    if (tid < HH)
        s_w1[tid] = make_float4(w1[3 * tid], w1[3 * tid + 1], w1[3 * tid + 2], b1[tid]);

    #pragma unroll
    for (int k = 0; k < 4; k++) {
        int idx = k * NTHREADS + tid;     // 0..1023
        int h = idx & (HH - 1);
        int pp = idx >> 7;                // 0..7
        s_w2p[h][pp] = make_float2(w2[(2 * pp) * HH + h], w2[(2 * pp + 1) * HH + h]);
    }
    if (tid < 8) s_b2p[tid] = make_float2(b2[2 * tid], b2[2 * tid + 1]);

    // ---- per-block rotation table (redundant across blocks by design) ----
    #pragma unroll
    for (int k = 0; k < 2; k++) {
        int e = k * NTHREADS + tid;       // 0..511 = t*16+p
        float a1x = p6d[e * 6 + 0], a1y = p6d[e * 6 + 1], a1z = p6d[e * 6 + 2];
        float a2x = p6d[e * 6 + 3], a2y = p6d[e * 6 + 4], a2z = p6d[e * 6 + 5];
        float inv = rsqrtf(a1x * a1x + a1y * a1y + a1z * a1z);
        float b1x = a1x * inv, b1y = a1y * inv, b1z = a1z * inv;
        float d = b1x * a2x + b1y * a2y + b1z * a2z;
        float cx = a2x - d * b1x, cy = a2y - d * b1y, cz = a2z - d * b1z;
        float inv2 = rsqrtf(cx * cx + cy * cy + cz * cz);
        float b2x = cx * inv2, b2y = cy * inv2, b2z = cz * inv2;
        float b3x = b1y * b2z - b1z * b2y;
        float b3y = b1z * b2x - b1x * b2z;
        float b3z = b1x * b2y - b1y * b2x;
        float t0 = pt[e * 3 + 0], t1 = pt[e * 3 + 1], t2 = pt[e * 3 + 2];
        float* r = s_R[e];
        r[0] = b1x; r[1] = b1y; r[2] = b1z;
        r[3] = b2x; r[4] = b2y; r[5] = b2z;
        r[6] = b3x; r[7] = b3y; r[8] = b3z;
        r[9] = t0;  r[10] = t1; r[11] = t2;
        if (blockIdx.x == 0) {
            float* o = out + OFF_TL + e * 16;
            o[0] = b1x; o[1] = b1y; o[2]  = b1z; o[3]  = t0;
            o[4] = b2x; o[5] = b2y; o[6]  = b2z; o[7]  = t1;
            o[8] = b3x; o[9] = b3y; o[10] = b3z; o[11] = t2;
            o[12] = 0.f; o[13] = 0.f; o[14] = 0.f; o[15] = 1.f;
        }
    }
    __syncthreads();

    // ---- warp-pair layout: pair handles 32 points, halves split h-range ----
    const int wid  = tid >> 5;
    const int lane = tid & 31;
    const int pair = wid >> 1;
    const int half = wid & 1;
    const int h0   = half * 64;
    const int p    = blockIdx.x * PTS_PER_BLOCK + pair * 32 + lane;

    const float xx = cano[p * 3], xy = cano[p * 3 + 1], xz = cano[p * 3 + 2];

    unsigned long long seg[8];
    #pragma unroll
    for (int k = 0; k < 8; k++) {
        unsigned long long bb = *reinterpret_cast<const unsigned long long*>(&s_b2p[k]);
        seg[k] = half ? 0ULL : bb;
    }

    // partial MLP over 64 hidden units (weight LDS = full-warp broadcast)
    #pragma unroll 4
    for (int hh = 0; hh < 64; hh++) {
        int h = h0 + hh;
        float4 w = s_w1[h];
        float hv = fmaxf(fmaf(xx, w.x, fmaf(xy, w.y, fmaf(xz, w.z, w.w))), 0.0f);
        unsigned long long h2 = packrep(hv);
        const ulonglong2* wp = reinterpret_cast<const ulonglong2*>(&s_w2p[h][0]);
        ulonglong2 q0 = wp[0], q1 = wp[1], q2 = wp[2], q3 = wp[3];
        fma2(seg[0], h2, q0.x);
        fma2(seg[1], h2, q0.y);
        fma2(seg[2], h2, q1.x);
        fma2(seg[3], h2, q1.y);
        fma2(seg[4], h2, q2.x);
        fma2(seg[5], h2, q2.y);
        fma2(seg[6], h2, q3.x);
        fma2(seg[7], h2, q3.y);
    }

    // odd half publishes its partial
    if (half) {
        #pragma unroll
        for (int k = 0; k < 8; k++)
            s_part[pair][k][lane] = seg[k];
    }
    __syncthreads();

    // even half reduces, computes argmax + gumbel selection
    if (!half) {
        float s[16];
        #pragma unroll
        for (int k = 0; k < 8; k++) {
            unsigned long long full = add2(seg[k], s_part[pair][k][lane]);
            unpack2(full, s[2 * k], s[2 * k + 1]);
        }

        // argmax(seg) — first-occurrence semantics
        int ia = 0; float m = s[0];
        #pragma unroll
        for (int q = 1; q < PP; q++)
            if (s[q] > m) { m = s[q]; ia = q; }
        out[OFF_ARG + p] = (float)ia;

        // argmax(seg + gumbel) — loaded here; 6.9 warps/SMSP hide the latency
        const float4* g4 = reinterpret_cast<const float4*>(gum + (size_t)p * PP);
        float4 g0 = g4[0], g1 = g4[1], g2 = g4[2], g3 = g4[3];
        const float gg[16] = { g0.x, g0.y, g0.z, g0.w, g1.x, g1.y, g1.z, g1.w,
                               g2.x, g2.y, g2.z, g2.w, g3.x, g3.y, g3.z, g3.w };
        int sl = 0; float vm = -1e30f;
        #pragma unroll
        for (int q = 0; q < PP; q++) {
            float a = s[q] + gg[q];
            if (a > vm) { vm = a; sl = q; }
        }
        s_sel[pair][lane] = sl;
    }
    __syncthreads();

    const int sel = s_sel[pair][lane];

    // epilogue split 16/16 over t between the pair's halves
    #pragma unroll 4
    for (int tt = 0; tt < 16; tt++) {
        int t = half * 16 + tt;
        const float4* R = reinterpret_cast<const float4*>(s_R[t * PP + sel]);
        float4 r0 = R[0], r1 = R[1], r2 = R[2];
        float o0 = fmaf(xx, r0.x, fmaf(xy, r0.y, fmaf(xz, r0.z, r2.y)));
        float o1 = fmaf(xx, r0.w, fmaf(xy, r1.x, fmaf(xz, r1.y, r2.z)));
        float o2 = fmaf(xx, r1.z, fmaf(xy, r1.w, fmaf(xz, r2.x, r2.w)));
        float* dst = out + (size_t)(t * NN + p) * 3;
        dst[0] = o0;
        dst[1] = o1;
        dst[2] = o2;
    }
}

extern "C" void kernel_launch(void* const* d_in, const int* in_sizes, int n_in,
                              void* d_out, int out_size) {
    (void)in_sizes; (void)n_in; (void)out_size;
    fused_kernel<<<NBLOCKS, NTHREADS>>>(
        (const float*)d_in[0],  // cano_pc
        (const float*)d_in[1],  // w1
        (const float*)d_in[2],  // b1
        (const float*)d_in[3],  // w2
        (const float*)d_in[4],  // b2
        (const float*)d_in[5],  // proposal_6d
        (const float*)d_in[6],  // proposal_t
        (const float*)d_in[7],  // gumbel
        (float*)d_out);
}